// round 4
// baseline (speedup 1.0000x reference)
#include <cuda_runtime.h>

// Problem constants
#define Bn   16
#define Nn   1024
#define Cn   768
#define Hn   12
#define HD   64
#define Mn   (Bn*Nn)      // 16384 tokens
#define QKVN (3*Cn)       // 2304

// Scratch (allocation-free rule: __device__ globals)
__device__ float g_Q[Bn*Hn*Nn*HD];   // [b,h,t,d], pre-scaled by 0.125
__device__ float g_K[Bn*Hn*Nn*HD];   // [b,h,t,d]
__device__ float g_V[Bn*Hn*Nn*HD];   // [b,h,t,d]
__device__ float g_O[(size_t)Mn*Cn]; // attention output, [b*N+t, h*64+d]

// ---------------------------------------------------------------------------
// Kernel 1: qkv = x @ W_qkv + b ; apply 2D RoPE to q,k ; scatter to g_Q/K/V
// 64x64 output tile per block, 256 threads, 4x4 micro-tile, K-step 32.
// ---------------------------------------------------------------------------
__global__ __launch_bounds__(256) void qkv_rope_kernel(
    const float* __restrict__ x, const float* __restrict__ W,
    const float* __restrict__ bias, const int* __restrict__ pos_h,
    const int* __restrict__ pos_w)
{
    __shared__ float sm[4352];          // main loop: As[32][64]+Bs[32][64]; epilogue: tile[64][66]
    float* As = sm;
    float* Bs = sm + 2048;

    const int tid = threadIdx.x;
    const int tx = tid & 15, ty = tid >> 4;
    const int m0 = blockIdx.y * 64;
    const int n0 = blockIdx.x * 64;

    float acc[4][4] = {};

    for (int k0 = 0; k0 < Cn; k0 += 32) {
        // A tile: x[m0:m0+64][k0:k0+32], stored transposed As[k][m]
        #pragma unroll
        for (int i = 0; i < 2; i++) {
            int idx = tid + i*256;            // 0..511
            int r = idx >> 3, c4 = idx & 7;   // r: 0..63, c4: 0..7
            float4 v = *reinterpret_cast<const float4*>(&x[(size_t)(m0 + r)*Cn + k0 + c4*4]);
            As[(c4*4+0)*64 + r] = v.x;
            As[(c4*4+1)*64 + r] = v.y;
            As[(c4*4+2)*64 + r] = v.z;
            As[(c4*4+3)*64 + r] = v.w;
        }
        // B tile: W[k0:k0+32][n0:n0+64] direct
        #pragma unroll
        for (int i = 0; i < 2; i++) {
            int idx = tid + i*256;
            int kr = idx >> 4, c4 = idx & 15;
            *reinterpret_cast<float4*>(&Bs[kr*64 + c4*4]) =
                *reinterpret_cast<const float4*>(&W[(size_t)(k0 + kr)*QKVN + n0 + c4*4]);
        }
        __syncthreads();
        #pragma unroll
        for (int kk = 0; kk < 32; kk++) {
            float4 a = *reinterpret_cast<const float4*>(&As[kk*64 + ty*4]);
            float4 b = *reinterpret_cast<const float4*>(&Bs[kk*64 + tx*4]);
            float av[4] = {a.x, a.y, a.z, a.w};
            float bv[4] = {b.x, b.y, b.z, b.w};
            #pragma unroll
            for (int ii = 0; ii < 4; ii++)
                #pragma unroll
                for (int jj = 0; jj < 4; jj++)
                    acc[ii][jj] += av[ii] * bv[jj];
        }
        __syncthreads();
    }

    // Epilogue
    const int which = n0 / Cn;            // 0=q 1=k 2=v (tile is fully inside one)
    const int h = (n0 % Cn) / HD;         // head (tile is fully inside one head)
    float bv4[4];
    #pragma unroll
    for (int jj = 0; jj < 4; jj++) bv4[jj] = bias[n0 + tx*4 + jj];

    if (which == 2) {
        // V: no rope, direct scatter to [b,h,t,d]
        #pragma unroll
        for (int ii = 0; ii < 4; ii++) {
            int m = m0 + ty*4 + ii;
            int b = m >> 10, t = m & 1023;
            float* dst = &g_V[(size_t)((b*Hn + h)*Nn + t)*HD + tx*4];
            #pragma unroll
            for (int jj = 0; jj < 4; jj++) dst[jj] = acc[ii][jj] + bv4[jj];
        }
    } else {
        // stage tile in smem so each element can read its rope partner (+-16 cols)
        float* tile = sm;                 // [64][66]
        #pragma unroll
        for (int ii = 0; ii < 4; ii++)
            #pragma unroll
            for (int jj = 0; jj < 4; jj++)
                tile[(ty*4+ii)*66 + tx*4 + jj] = acc[ii][jj] + bv4[jj];
        __syncthreads();

        float* base = (which == 0) ? g_Q : g_K;
        const float qscale = (which == 0) ? 0.125f : 1.0f;   // fold hd^-0.5 into Q
        #pragma unroll
        for (int ii = 0; ii < 4; ii++) {
            int r = ty*4 + ii;
            int m = m0 + r;
            int b = m >> 10, t = m & 1023;
            int ph = pos_h[m], pw = pos_w[m];
            float* dst = base + (size_t)((b*Hn + h)*Nn + t)*HD;
            #pragma unroll
            for (int jj = 0; jj < 4; jj++) {
                int d = tx*4 + jj;
                int half = d >> 5;        // 0: pos_h half, 1: pos_w half
                int j = d & 31;           // index within half
                int f = j >> 1;           // freq index (cos/sin repeated x2)
                // inv[f] = 10000^(-f/16) = 2^(-f*log2(10000)/16)
                float invf = exp2f(-(float)f * (13.287712379549449f / 16.0f));
                float pos = (float)(half ? pw : ph);
                float sn, cs;
                sincosf(pos * invf, &sn, &cs);
                int cp = half*32 + ((j < 16) ? (j + 16) : (j - 16));
                float partner = tile[r*66 + cp];
                float rot = (j < 16) ? -partner : partner;
                float val = tile[r*66 + d]*cs + rot*sn;
                dst[d] = val * qscale;
            }
        }
    }
}

// ---------------------------------------------------------------------------
// Kernel 2: flash-style attention per (b,h, 64-row q tile). fp32, online softmax.
// smem: Qs[d][r] 16KB, Ks[d][j] 16KB (reused as Ps[j][i]), Vs[j][d] 16KB = 48KB
// ---------------------------------------------------------------------------
__global__ __launch_bounds__(256) void attn_kernel()
{
    __shared__ float Qs[64*64];
    __shared__ float Ks[64*64];
    __shared__ float Vs[64*64];
    float* Ps = Ks;

    const int tid = threadIdx.x;
    const int tx = tid & 15, ty = tid >> 4;
    const int qt = blockIdx.x;            // 0..15
    const int bh = blockIdx.y;            // 0..191
    const int b = bh / Hn, h = bh % Hn;
    const float* Qg = g_Q + (size_t)bh * Nn * HD;
    const float* Kg = g_K + (size_t)bh * Nn * HD;
    const float* Vg = g_V + (size_t)bh * Nn * HD;
    const int t0 = qt * 64;

    // Load Q tile transposed: Qs[d][r]
    #pragma unroll
    for (int i = 0; i < 4; i++) {
        int idx = tid + i*256;            // 0..1023
        int r = idx >> 4, d4 = idx & 15;
        float4 v = *reinterpret_cast<const float4*>(&Qg[(size_t)(t0 + r)*HD + d4*4]);
        Qs[(d4*4+0)*64 + r] = v.x;
        Qs[(d4*4+1)*64 + r] = v.y;
        Qs[(d4*4+2)*64 + r] = v.z;
        Qs[(d4*4+3)*64 + r] = v.w;
    }

    float mi[4], li[4], o[4][4];
    #pragma unroll
    for (int ii = 0; ii < 4; ii++) {
        mi[ii] = -1e30f; li[ii] = 0.f;
        #pragma unroll
        for (int jj = 0; jj < 4; jj++) o[ii][jj] = 0.f;
    }

    for (int kt = 0; kt < 16; kt++) {
        __syncthreads();  // previous iter's Ps/Vs reads done (also orders first Qs fill)
        // Load K tile transposed Ks[d][j]; V tile direct Vs[j][d]
        #pragma unroll
        for (int i = 0; i < 4; i++) {
            int idx = tid + i*256;
            int r = idx >> 4, d4 = idx & 15;
            float4 kv = *reinterpret_cast<const float4*>(&Kg[(size_t)(kt*64 + r)*HD + d4*4]);
            Ks[(d4*4+0)*64 + r] = kv.x;
            Ks[(d4*4+1)*64 + r] = kv.y;
            Ks[(d4*4+2)*64 + r] = kv.z;
            Ks[(d4*4+3)*64 + r] = kv.w;
            *reinterpret_cast<float4*>(&Vs[r*64 + d4*4]) =
                *reinterpret_cast<const float4*>(&Vg[(size_t)(kt*64 + r)*HD + d4*4]);
        }
        __syncthreads();

        // S = (Q*0.125) @ K^T  (scale already folded into Q)
        float s[4][4] = {};
        #pragma unroll 8
        for (int d = 0; d < 64; d++) {
            float4 a = *reinterpret_cast<const float4*>(&Qs[d*64 + ty*4]);
            float4 k4 = *reinterpret_cast<const float4*>(&Ks[d*64 + tx*4]);
            float av[4] = {a.x, a.y, a.z, a.w};
            float kvv[4] = {k4.x, k4.y, k4.z, k4.w};
            #pragma unroll
            for (int ii = 0; ii < 4; ii++)
                #pragma unroll
                for (int jj = 0; jj < 4; jj++)
                    s[ii][jj] += av[ii] * kvv[jj];
        }

        // online softmax (rows shared across the 16 tx lanes of each half-warp)
        #pragma unroll
        for (int ii = 0; ii < 4; ii++) {
            float rm = fmaxf(fmaxf(s[ii][0], s[ii][1]), fmaxf(s[ii][2], s[ii][3]));
            #pragma unroll
            for (int off = 8; off >= 1; off >>= 1)
                rm = fmaxf(rm, __shfl_xor_sync(0xffffffffu, rm, off));
            float newm = fmaxf(mi[ii], rm);
            float corr = __expf(mi[ii] - newm);
            mi[ii] = newm;
            float rs = 0.f;
            #pragma unroll
            for (int jj = 0; jj < 4; jj++) {
                float p = __expf(s[ii][jj] - newm);
                s[ii][jj] = p;
                rs += p;
            }
            #pragma unroll
            for (int off = 8; off >= 1; off >>= 1)
                rs += __shfl_xor_sync(0xffffffffu, rs, off);
            li[ii] = li[ii]*corr + rs;
            #pragma unroll
            for (int jj = 0; jj < 4; jj++) o[ii][jj] *= corr;
        }

        __syncthreads();                  // everyone done reading Ks before Ps overwrite
        #pragma unroll
        for (int ii = 0; ii < 4; ii++)
            #pragma unroll
            for (int jj = 0; jj < 4; jj++)
                Ps[(tx*4+jj)*64 + ty*4 + ii] = s[ii][jj];
        __syncthreads();

        // O += P @ V
        #pragma unroll 8
        for (int j = 0; j < 64; j++) {
            float4 p4 = *reinterpret_cast<const float4*>(&Ps[j*64 + ty*4]);
            float4 v4 = *reinterpret_cast<const float4*>(&Vs[j*64 + tx*4]);
            float pv[4] = {p4.x, p4.y, p4.z, p4.w};
            float vv[4] = {v4.x, v4.y, v4.z, v4.w};
            #pragma unroll
            for (int ii = 0; ii < 4; ii++)
                #pragma unroll
                for (int jj = 0; jj < 4; jj++)
                    o[ii][jj] += pv[ii] * vv[jj];
        }
    }

    // epilogue: normalize, write O in [b*N+t][h*64+d] layout (proj-ready)
    #pragma unroll
    for (int ii = 0; ii < 4; ii++) {
        float inv = 1.0f / li[ii];
        int t = t0 + ty*4 + ii;
        float* dst = &g_O[(size_t)(b*Nn + t)*Cn + h*HD + tx*4];
        #pragma unroll
        for (int jj = 0; jj < 4; jj++) dst[jj] = o[ii][jj] * inv;
    }
}

// ---------------------------------------------------------------------------
// Kernel 3: out = g_O @ W_proj + b_proj
// ---------------------------------------------------------------------------
__global__ __launch_bounds__(256) void proj_kernel(
    const float* __restrict__ W, const float* __restrict__ bias,
    float* __restrict__ out)
{
    __shared__ float sm[4096];
    float* As = sm;
    float* Bs = sm + 2048;

    const int tid = threadIdx.x;
    const int tx = tid & 15, ty = tid >> 4;
    const int m0 = blockIdx.y * 64;
    const int n0 = blockIdx.x * 64;

    float acc[4][4] = {};

    for (int k0 = 0; k0 < Cn; k0 += 32) {
        #pragma unroll
        for (int i = 0; i < 2; i++) {
            int idx = tid + i*256;
            int r = idx >> 3, c4 = idx & 7;
            float4 v = *reinterpret_cast<const float4*>(&g_O[(size_t)(m0 + r)*Cn + k0 + c4*4]);
            As[(c4*4+0)*64 + r] = v.x;
            As[(c4*4+1)*64 + r] = v.y;
            As[(c4*4+2)*64 + r] = v.z;
            As[(c4*4+3)*64 + r] = v.w;
        }
        #pragma unroll
        for (int i = 0; i < 2; i++) {
            int idx = tid + i*256;
            int kr = idx >> 4, c4 = idx & 15;
            *reinterpret_cast<float4*>(&Bs[kr*64 + c4*4]) =
                *reinterpret_cast<const float4*>(&W[(size_t)(k0 + kr)*Cn + n0 + c4*4]);
        }
        __syncthreads();
        #pragma unroll
        for (int kk = 0; kk < 32; kk++) {
            float4 a = *reinterpret_cast<const float4*>(&As[kk*64 + ty*4]);
            float4 b = *reinterpret_cast<const float4*>(&Bs[kk*64 + tx*4]);
            float av[4] = {a.x, a.y, a.z, a.w};
            float bv[4] = {b.x, b.y, b.z, b.w};
            #pragma unroll
            for (int ii = 0; ii < 4; ii++)
                #pragma unroll
                for (int jj = 0; jj < 4; jj++)
                    acc[ii][jj] += av[ii] * bv[jj];
        }
        __syncthreads();
    }

    #pragma unroll
    for (int ii = 0; ii < 4; ii++) {
        int m = m0 + ty*4 + ii;
        float4 r;
        r.x = acc[ii][0] + bias[n0 + tx*4 + 0];
        r.y = acc[ii][1] + bias[n0 + tx*4 + 1];
        r.z = acc[ii][2] + bias[n0 + tx*4 + 2];
        r.w = acc[ii][3] + bias[n0 + tx*4 + 3];
        *reinterpret_cast<float4*>(&out[(size_t)m*Cn + n0 + tx*4]) = r;
    }
}

// ---------------------------------------------------------------------------
extern "C" void kernel_launch(void* const* d_in, const int* in_sizes, int n_in,
                              void* d_out, int out_size)
{
    const float* x     = (const float*)d_in[0];
    const float* Wqkv  = (const float*)d_in[1];
    const float* bqkv  = (const float*)d_in[2];
    const float* Wproj = (const float*)d_in[3];
    const float* bproj = (const float*)d_in[4];
    const int*   pos_h = (const int*)d_in[5];
    const int*   pos_w = (const int*)d_in[6];
    float* out = (float*)d_out;

    dim3 g1(QKVN/64, Mn/64);     // 36 x 256
    qkv_rope_kernel<<<g1, 256>>>(x, Wqkv, bqkv, pos_h, pos_w);

    dim3 g2(Nn/64, Bn*Hn);       // 16 x 192
    attn_kernel<<<g2, 256>>>();

    dim3 g3(Cn/64, Mn/64);       // 12 x 256
    proj_kernel<<<g3, 256>>>(Wproj, bproj, out);
}

// round 5
// speedup vs baseline: 2.3310x; 2.3310x over previous
#include <cuda_runtime.h>
#include <cstdint>
#include <cstddef>

// Problem constants
#define Bn   16
#define Nn   1024
#define Cn   768
#define Hn   12
#define HD   64
#define Mn   (Bn*Nn)      // 16384 tokens
#define QKVN (3*Cn)       // 2304

// Scratch (allocation-free rule: __device__ globals)
__device__ float g_Q[(size_t)Bn*Hn*Nn*HD];   // [b,h,t,d], tf32-rounded, pre-scaled 0.125
__device__ float g_K[(size_t)Bn*Hn*Nn*HD];   // [b,h,t,d], tf32-rounded
__device__ float g_V[(size_t)Bn*Hn*Nn*HD];   // [b,h,t,d], tf32-rounded
__device__ float g_O[(size_t)Mn*Cn];         // attention out, [b*N+t][h*64+d]

// ---------------------------------------------------------------------------
// tf32 helpers
// ---------------------------------------------------------------------------
__device__ __forceinline__ uint32_t f2tf_bits(float v) {
    uint32_t r;
    asm("cvt.rna.tf32.f32 %0, %1;" : "=r"(r) : "f"(v));
    return r;
}
__device__ __forceinline__ float tf32r(float v) { return __uint_as_float(f2tf_bits(v)); }

// D += A(16x8,row) * B(8x8,col) ; tf32 inputs, fp32 accum
__device__ __forceinline__ void mma_tf32(float d[4], const uint32_t a[4],
                                         uint32_t b0, uint32_t b1) {
    asm volatile(
        "mma.sync.aligned.m16n8k8.row.col.f32.tf32.tf32.f32 "
        "{%0,%1,%2,%3},{%4,%5,%6,%7},{%8,%9},{%0,%1,%2,%3};"
        : "+f"(d[0]), "+f"(d[1]), "+f"(d[2]), "+f"(d[3])
        : "r"(a[0]), "r"(a[1]), "r"(a[2]), "r"(a[3]), "r"(b0), "r"(b1));
}

// ---------------------------------------------------------------------------
// 3xTF32 GEMM core: 128(M) x 64(N) block tile, BK=32, K=768 fixed.
// 8 warps = 4(m) x 2(n); warp tile 32x32 = 2 m16 x 4 n8.
// smem: Ahi/Alo [128][36], Bhi/Blo [32][72]  (pads -> conflict-free frag loads)
// ---------------------------------------------------------------------------
#define A_STR 36
#define B_STR 72
#define SM_ALO (128*A_STR)           // 4608
#define SM_BHI (2*128*A_STR)         // 9216
#define SM_BLO (SM_BHI + 32*B_STR)   // 11520
#define GEMM_SMEM_FLOATS (SM_BLO + 32*B_STR)   // 13824
#define GEMM_SMEM_BYTES  (GEMM_SMEM_FLOATS*4)  // 55296
#define ATTN_SMEM_BYTES  (17664*4)             // 70656

template<int BLD>
__device__ __forceinline__ void gemm_128x64_3xtf32(
    const float* __restrict__ A, const float* __restrict__ Bm,
    int m0, int n0, float* sm, float acc[2][4][4])
{
    const int tid  = threadIdx.x;
    const int lane = tid & 31, warp = tid >> 5;
    const int wm = warp >> 1, wn = warp & 1;
    const int g = lane >> 2, tig = lane & 3;
    float* Ahi = sm;
    float* Alo = sm + SM_ALO;
    float* Bhi = sm + SM_BHI;
    float* Blo = sm + SM_BLO;

    for (int k0 = 0; k0 < Cn; k0 += 32) {
        // stage A 128x32 (hi/lo split, once per element)
        #pragma unroll
        for (int i = 0; i < 4; i++) {
            int idx = tid + i*256;
            int r = idx >> 3, c = idx & 7;
            float4 v = *reinterpret_cast<const float4*>(&A[(size_t)(m0+r)*Cn + k0 + c*4]);
            float4 h, l;
            h.x = tf32r(v.x); l.x = tf32r(v.x - h.x);
            h.y = tf32r(v.y); l.y = tf32r(v.y - h.y);
            h.z = tf32r(v.z); l.z = tf32r(v.z - h.z);
            h.w = tf32r(v.w); l.w = tf32r(v.w - h.w);
            *reinterpret_cast<float4*>(&Ahi[r*A_STR + c*4]) = h;
            *reinterpret_cast<float4*>(&Alo[r*A_STR + c*4]) = l;
        }
        // stage B 32x64
        #pragma unroll
        for (int i = 0; i < 2; i++) {
            int idx = tid + i*256;
            int r = idx >> 4, c = idx & 15;
            float4 v = *reinterpret_cast<const float4*>(&Bm[(size_t)(k0+r)*BLD + n0 + c*4]);
            float4 h, l;
            h.x = tf32r(v.x); l.x = tf32r(v.x - h.x);
            h.y = tf32r(v.y); l.y = tf32r(v.y - h.y);
            h.z = tf32r(v.z); l.z = tf32r(v.z - h.z);
            h.w = tf32r(v.w); l.w = tf32r(v.w - h.w);
            *reinterpret_cast<float4*>(&Bhi[r*B_STR + c*4]) = h;
            *reinterpret_cast<float4*>(&Blo[r*B_STR + c*4]) = l;
        }
        __syncthreads();

        #pragma unroll
        for (int kb = 0; kb < 4; kb++) {
            uint32_t ah[2][4], al[2][4];
            #pragma unroll
            for (int mt = 0; mt < 2; mt++) {
                int row = wm*32 + mt*16 + g;
                int col = kb*8 + tig;
                ah[mt][0] = __float_as_uint(Ahi[row*A_STR + col]);
                ah[mt][1] = __float_as_uint(Ahi[(row+8)*A_STR + col]);
                ah[mt][2] = __float_as_uint(Ahi[row*A_STR + col + 4]);
                ah[mt][3] = __float_as_uint(Ahi[(row+8)*A_STR + col + 4]);
                al[mt][0] = __float_as_uint(Alo[row*A_STR + col]);
                al[mt][1] = __float_as_uint(Alo[(row+8)*A_STR + col]);
                al[mt][2] = __float_as_uint(Alo[row*A_STR + col + 4]);
                al[mt][3] = __float_as_uint(Alo[(row+8)*A_STR + col + 4]);
            }
            #pragma unroll
            for (int nt = 0; nt < 4; nt++) {
                int col = wn*32 + nt*8 + g;
                int row = kb*8 + tig;
                uint32_t bh0 = __float_as_uint(Bhi[row*B_STR + col]);
                uint32_t bh1 = __float_as_uint(Bhi[(row+4)*B_STR + col]);
                uint32_t bl0 = __float_as_uint(Blo[row*B_STR + col]);
                uint32_t bl1 = __float_as_uint(Blo[(row+4)*B_STR + col]);
                #pragma unroll
                for (int mt = 0; mt < 2; mt++) {
                    mma_tf32(acc[mt][nt], ah[mt], bh0, bh1);  // hi*hi
                    mma_tf32(acc[mt][nt], ah[mt], bl0, bl1);  // hi*lo
                    mma_tf32(acc[mt][nt], al[mt], bh0, bh1);  // lo*hi
                }
            }
        }
        __syncthreads();
    }
}

// ---------------------------------------------------------------------------
// Kernel 1: qkv = x @ W_qkv + b ; 2D RoPE on q,k ; tf32-round ; scatter
// ---------------------------------------------------------------------------
__global__ __launch_bounds__(256) void qkv_rope_kernel(
    const float* __restrict__ x, const float* __restrict__ W,
    const float* __restrict__ bias, const int* __restrict__ pos_h,
    const int* __restrict__ pos_w)
{
    extern __shared__ float sm[];
    const int m0 = blockIdx.y * 128;
    const int n0 = blockIdx.x * 64;

    float acc[2][4][4] = {};
    gemm_128x64_3xtf32<QKVN>(x, W, m0, n0, sm, acc);
    __syncthreads();   // all frag reads done before smem reuse

    const int tid  = threadIdx.x;
    const int lane = tid & 31, warp = tid >> 5;
    const int wm = warp >> 1, wn = warp & 1;
    const int g = lane >> 2, tig = lane & 3;

    // stage acc+bias into Es[128][66] (fits inside Ahi/Alo region)
    float* Es = sm;
    #pragma unroll
    for (int mt = 0; mt < 2; mt++) {
        #pragma unroll
        for (int nt = 0; nt < 4; nt++) {
            int row = wm*32 + mt*16 + g;
            int col = wn*32 + nt*8 + 2*tig;
            float b0 = bias[n0 + col], b1 = bias[n0 + col + 1];
            Es[row*66 + col]       = acc[mt][nt][0] + b0;
            Es[row*66 + col + 1]   = acc[mt][nt][1] + b1;
            Es[(row+8)*66 + col]   = acc[mt][nt][2] + b0;
            Es[(row+8)*66 + col+1] = acc[mt][nt][3] + b1;
        }
    }
    __syncthreads();

    const int which = n0 / Cn;           // 0=q 1=k 2=v
    const int h     = (n0 % Cn) / HD;
    float* base = (which == 0) ? g_Q : ((which == 1) ? g_K : g_V);
    const float qscale = (which == 0) ? 0.125f : 1.0f;

    const int tx = tid & 15, tyy = tid >> 4;
    #pragma unroll
    for (int ii = 0; ii < 8; ii++) {
        int r = tyy*8 + ii;
        int m = m0 + r;
        int b = m >> 10, t = m & 1023;
        float* dst = base + ((size_t)(b*Hn + h)*Nn + t)*HD;
        if (which == 2) {
            #pragma unroll
            for (int jj = 0; jj < 4; jj++) {
                int d = tx*4 + jj;
                dst[d] = tf32r(Es[r*66 + d]);
            }
        } else {
            int ph = pos_h[m], pw = pos_w[m];
            #pragma unroll
            for (int jj = 0; jj < 4; jj++) {
                int d = tx*4 + jj;
                int half = d >> 5;
                int j = d & 31;
                int f = j >> 1;
                float invf = exp2f(-(float)f * (13.287712379549449f / 16.0f));
                float pos = (float)(half ? pw : ph);
                float sn, cs;
                sincosf(pos * invf, &sn, &cs);
                int cp = half*32 + ((j < 16) ? (j + 16) : (j - 16));
                float partner = Es[r*66 + cp];
                float rot = (j < 16) ? -partner : partner;
                float val = Es[r*66 + d]*cs + rot*sn;
                dst[d] = tf32r(val * qscale);
            }
        }
    }
}

// ---------------------------------------------------------------------------
// Kernel 2: flash attention, single-pass tf32 mma.
// Block: 128 q rows x full key loop; 8 warps, warp owns 16 q rows (full softmax
// rows -> no cross-warp reduction). K/V tiles 64 keys/iter.
// smem: Qs[128][68] (reused as P), Ks[64][68], Vs[64][72]
// ---------------------------------------------------------------------------
__global__ __launch_bounds__(256) void attn_kernel()
{
    extern __shared__ float sm[];
    float* Qs = sm;            // 128*68 = 8704 ; reused as P after frag extract
    float* Ks = sm + 8704;     // 64*68  = 4352
    float* Vs = sm + 13056;    // 64*72  = 4608

    const int tid  = threadIdx.x;
    const int lane = tid & 31, w = tid >> 5;
    const int g = lane >> 2, tig = lane & 3;
    const int qt = blockIdx.x;            // 0..7
    const int bh = blockIdx.y;            // 0..191  (= b*Hn + h)
    const int b  = bh / Hn, h = bh % Hn;
    const float* Qg = g_Q + (size_t)bh * Nn * HD;
    const float* Kg = g_K + (size_t)bh * Nn * HD;
    const float* Vg = g_V + (size_t)bh * Nn * HD;
    const int t0 = qt * 128;

    // stage Q tile (coalesced), then extract per-warp A-fragments to registers
    #pragma unroll
    for (int i = 0; i < 8; i++) {
        int idx = tid + i*256;
        int r = idx >> 4, c = idx & 15;
        *reinterpret_cast<float4*>(&Qs[r*68 + c*4]) =
            *reinterpret_cast<const float4*>(&Qg[(size_t)(t0 + r)*HD + c*4]);
    }
    __syncthreads();

    const int qrow = w*16 + g;            // warp-local row (and +8)
    uint32_t qa[8][4];
    #pragma unroll
    for (int kb = 0; kb < 8; kb++) {
        qa[kb][0] = __float_as_uint(Qs[qrow*68 + kb*8 + tig]);
        qa[kb][1] = __float_as_uint(Qs[(qrow+8)*68 + kb*8 + tig]);
        qa[kb][2] = __float_as_uint(Qs[qrow*68 + kb*8 + tig + 4]);
        qa[kb][3] = __float_as_uint(Qs[(qrow+8)*68 + kb*8 + tig + 4]);
    }

    float o[8][4] = {};
    float m0_ = -1e30f, m1_ = -1e30f, l0_ = 0.f, l1_ = 0.f;

    for (int kt = 0; kt < 16; kt++) {
        __syncthreads();   // prior iter's Ks/Vs reads (and Q extract) complete
        #pragma unroll
        for (int i = 0; i < 4; i++) {
            int idx = tid + i*256;
            int r = idx >> 4, c = idx & 15;
            *reinterpret_cast<float4*>(&Ks[r*68 + c*4]) =
                *reinterpret_cast<const float4*>(&Kg[(size_t)(kt*64 + r)*HD + c*4]);
            *reinterpret_cast<float4*>(&Vs[r*72 + c*4]) =
                *reinterpret_cast<const float4*>(&Vg[(size_t)(kt*64 + r)*HD + c*4]);
        }
        __syncthreads();

        // S = Q @ K^T (scale pre-folded into Q)
        float s[8][4] = {};
        #pragma unroll
        for (int kb = 0; kb < 8; kb++) {
            #pragma unroll
            for (int nt = 0; nt < 8; nt++) {
                uint32_t b0 = __float_as_uint(Ks[(nt*8 + g)*68 + kb*8 + tig]);
                uint32_t b1 = __float_as_uint(Ks[(nt*8 + g)*68 + kb*8 + tig + 4]);
                mma_tf32(s[nt], qa[kb], b0, b1);
            }
        }

        // online softmax (rows fully warp-local; reduce over 4 tig lanes)
        float rm0 = -1e30f, rm1 = -1e30f;
        #pragma unroll
        for (int nt = 0; nt < 8; nt++) {
            rm0 = fmaxf(rm0, fmaxf(s[nt][0], s[nt][1]));
            rm1 = fmaxf(rm1, fmaxf(s[nt][2], s[nt][3]));
        }
        rm0 = fmaxf(rm0, __shfl_xor_sync(0xffffffffu, rm0, 1));
        rm0 = fmaxf(rm0, __shfl_xor_sync(0xffffffffu, rm0, 2));
        rm1 = fmaxf(rm1, __shfl_xor_sync(0xffffffffu, rm1, 1));
        rm1 = fmaxf(rm1, __shfl_xor_sync(0xffffffffu, rm1, 2));

        float nm0 = fmaxf(m0_, rm0), nm1 = fmaxf(m1_, rm1);
        float c0 = __expf(m0_ - nm0), c1 = __expf(m1_ - nm1);
        m0_ = nm0; m1_ = nm1;

        float rs0 = 0.f, rs1 = 0.f;
        #pragma unroll
        for (int nt = 0; nt < 8; nt++) {
            s[nt][0] = __expf(s[nt][0] - nm0);
            s[nt][1] = __expf(s[nt][1] - nm0);
            s[nt][2] = __expf(s[nt][2] - nm1);
            s[nt][3] = __expf(s[nt][3] - nm1);
            rs0 += s[nt][0] + s[nt][1];
            rs1 += s[nt][2] + s[nt][3];
        }
        rs0 += __shfl_xor_sync(0xffffffffu, rs0, 1);
        rs0 += __shfl_xor_sync(0xffffffffu, rs0, 2);
        rs1 += __shfl_xor_sync(0xffffffffu, rs1, 1);
        rs1 += __shfl_xor_sync(0xffffffffu, rs1, 2);
        l0_ = l0_*c0 + rs0;
        l1_ = l1_*c1 + rs1;
        #pragma unroll
        for (int nt = 0; nt < 8; nt++) {
            o[nt][0] *= c0; o[nt][1] *= c0;
            o[nt][2] *= c1; o[nt][3] *= c1;
        }

        // store P (tf32-rounded) to warp-private rows of the Q buffer
        float* P = Qs;
        __syncwarp();      // prior PV loads from P region done
        #pragma unroll
        for (int nt = 0; nt < 8; nt++) {
            P[qrow*68 + nt*8 + 2*tig]       = tf32r(s[nt][0]);
            P[qrow*68 + nt*8 + 2*tig + 1]   = tf32r(s[nt][1]);
            P[(qrow+8)*68 + nt*8 + 2*tig]   = tf32r(s[nt][2]);
            P[(qrow+8)*68 + nt*8 + 2*tig+1] = tf32r(s[nt][3]);
        }
        __syncwarp();

        // O += P @ V
        #pragma unroll
        for (int kb = 0; kb < 8; kb++) {
            uint32_t pa[4];
            pa[0] = __float_as_uint(P[qrow*68 + kb*8 + tig]);
            pa[1] = __float_as_uint(P[(qrow+8)*68 + kb*8 + tig]);
            pa[2] = __float_as_uint(P[qrow*68 + kb*8 + tig + 4]);
            pa[3] = __float_as_uint(P[(qrow+8)*68 + kb*8 + tig + 4]);
            #pragma unroll
            for (int nt = 0; nt < 8; nt++) {
                uint32_t b0 = __float_as_uint(Vs[(kb*8 + tig)*72 + nt*8 + g]);
                uint32_t b1 = __float_as_uint(Vs[(kb*8 + tig + 4)*72 + nt*8 + g]);
                mma_tf32(o[nt], pa, b0, b1);
            }
        }
    }

    // epilogue: normalize, write [b*N+t][h*64+d]
    float inv0 = 1.0f / l0_, inv1 = 1.0f / l1_;
    int trow = t0 + qrow;
    #pragma unroll
    for (int nt = 0; nt < 8; nt++) {
        int col = h*HD + nt*8 + 2*tig;
        float2 v0 = make_float2(o[nt][0]*inv0, o[nt][1]*inv0);
        float2 v1 = make_float2(o[nt][2]*inv1, o[nt][3]*inv1);
        *reinterpret_cast<float2*>(&g_O[((size_t)(b*Nn + trow))*Cn + col])     = v0;
        *reinterpret_cast<float2*>(&g_O[((size_t)(b*Nn + trow + 8))*Cn + col]) = v1;
    }
}

// ---------------------------------------------------------------------------
// Kernel 3: out = g_O @ W_proj + b_proj  (3xTF32)
// ---------------------------------------------------------------------------
__global__ __launch_bounds__(256) void proj_kernel(
    const float* __restrict__ W, const float* __restrict__ bias,
    float* __restrict__ out)
{
    extern __shared__ float sm[];
    const int m0 = blockIdx.y * 128;
    const int n0 = blockIdx.x * 64;

    float acc[2][4][4] = {};
    gemm_128x64_3xtf32<Cn>(g_O, W, m0, n0, sm, acc);

    const int tid  = threadIdx.x;
    const int lane = tid & 31, warp = tid >> 5;
    const int wm = warp >> 1, wn = warp & 1;
    const int g = lane >> 2, tig = lane & 3;

    #pragma unroll
    for (int mt = 0; mt < 2; mt++) {
        #pragma unroll
        for (int nt = 0; nt < 4; nt++) {
            int row = m0 + wm*32 + mt*16 + g;
            int col = n0 + wn*32 + nt*8 + 2*tig;
            float b0 = bias[col], b1 = bias[col + 1];
            float2 v0 = make_float2(acc[mt][nt][0] + b0, acc[mt][nt][1] + b1);
            float2 v1 = make_float2(acc[mt][nt][2] + b0, acc[mt][nt][3] + b1);
            *reinterpret_cast<float2*>(&out[(size_t)row*Cn + col])     = v0;
            *reinterpret_cast<float2*>(&out[(size_t)(row+8)*Cn + col]) = v1;
        }
    }
}

// ---------------------------------------------------------------------------
extern "C" void kernel_launch(void* const* d_in, const int* in_sizes, int n_in,
                              void* d_out, int out_size)
{
    const float* x     = (const float*)d_in[0];
    const float* Wqkv  = (const float*)d_in[1];
    const float* bqkv  = (const float*)d_in[2];
    const float* Wproj = (const float*)d_in[3];
    const float* bproj = (const float*)d_in[4];
    const int*   pos_h = (const int*)d_in[5];
    const int*   pos_w = (const int*)d_in[6];
    float* out = (float*)d_out;

    cudaFuncSetAttribute(qkv_rope_kernel,
                         cudaFuncAttributeMaxDynamicSharedMemorySize, GEMM_SMEM_BYTES);
    cudaFuncSetAttribute(attn_kernel,
                         cudaFuncAttributeMaxDynamicSharedMemorySize, ATTN_SMEM_BYTES);
    cudaFuncSetAttribute(proj_kernel,
                         cudaFuncAttributeMaxDynamicSharedMemorySize, GEMM_SMEM_BYTES);

    dim3 g1(QKVN/64, Mn/128);    // 36 x 128
    qkv_rope_kernel<<<g1, 256, GEMM_SMEM_BYTES>>>(x, Wqkv, bqkv, pos_h, pos_w);

    dim3 g2(Nn/128, Bn*Hn);      // 8 x 192
    attn_kernel<<<g2, 256, ATTN_SMEM_BYTES>>>();

    dim3 g3(Cn/64, Mn/128);      // 12 x 128
    proj_kernel<<<g3, 256, GEMM_SMEM_BYTES>>>(Wproj, bproj, out);
}